// round 14
// baseline (speedup 1.0000x reference)
#include <cuda_runtime.h>
#include <cuda_fp16.h>
#include <math.h>
#include <stdint.h>

#define NN 32768
#define DD 768
#define CC 1024
#define MUF 0.9f
#define LAMF 0.5f

// ===================== PTX helpers =====================
__device__ __forceinline__ uint32_t smem_u32(const void* p){
    uint32_t a;
    asm("{ .reg .u64 t; cvta.to.shared.u64 t, %1; cvt.u32.u64 %0, t; }" : "=r"(a) : "l"(p));
    return a;
}
#define CPA16(d,s)  asm volatile("cp.async.cg.shared.global [%0], [%1], 16;"::"r"(d),"l"(s))
#define CPCOMMIT()  asm volatile("cp.async.commit_group;":::"memory")
#define CPWAIT(n)   asm volatile("cp.async.wait_group %0;"::"n"(n):"memory")

__device__ __forceinline__ void ldsm4(uint32_t* r, uint32_t addr){
    asm volatile("ldmatrix.sync.aligned.m8n8.x4.shared.b16 {%0,%1,%2,%3}, [%4];"
        : "=r"(r[0]), "=r"(r[1]), "=r"(r[2]), "=r"(r[3]) : "r"(addr));
}
__device__ __forceinline__ void mma_fp16(float* c, const uint32_t* a, uint32_t b0, uint32_t b1){
    asm volatile(
        "mma.sync.aligned.m16n8k16.row.col.f32.f16.f16.f32 "
        "{%0,%1,%2,%3}, {%4,%5,%6,%7}, {%8,%9}, {%0,%1,%2,%3};"
        : "+f"(c[0]), "+f"(c[1]), "+f"(c[2]), "+f"(c[3])
        : "r"(a[0]), "r"(a[1]), "r"(a[2]), "r"(a[3]), "r"(b0), "r"(b1));
}

// ===================== scratch =====================
__device__ half g_xh[(size_t)NN*DD];
__device__ half g_cxh[(size_t)NN*DD];
__device__ half g_hh[(size_t)NN*DD];
__device__ half g_uh[(size_t)NN*DD];
__device__ half g_ctxh[(size_t)NN*CC];
__device__ half g_wlh[(size_t)NN*CC];
__device__ half g_vth[DD*CC];
__device__ half g_Wch[CC*DD];
__device__ half g_W1h[DD*DD];
__device__ half g_W2h[CC*DD];
__device__ half g_Kh[CC*DD];
__device__ float g_buf[(size_t)NN*CC];
__device__ float g_gate[NN];
__device__ float g_red[(size_t)(CC-1)*DD + (CC-1) + 8];
#define g_sums (g_red)
#define g_cnts (g_red + (size_t)(CC-1)*DD)
#define g_acc  (g_red + (size_t)(CC-1)*DD + (CC-1))

// ===================== side stream =====================
struct SideStream {
    cudaStream_t s = 0;
    cudaEvent_t fork = 0, join = 0;
    bool ok = false;
    SideStream(){
        if (cudaStreamCreateWithFlags(&s, cudaStreamNonBlocking) == cudaSuccess &&
            cudaEventCreateWithFlags(&fork, cudaEventDisableTiming) == cudaSuccess &&
            cudaEventCreateWithFlags(&join, cudaEventDisableTiming) == cudaSuccess)
            ok = true;
    }
};
static SideStream g_ss;

// ===================== cvt kernels =====================
__device__ __forceinline__ void cvt8(const float* __restrict__ s,
                                     half* __restrict__ d, size_t i){
    float4 a = ((const float4*)s)[2*i], b = ((const float4*)s)[2*i+1];
    half2 h0 = __floats2half2_rn(a.x, a.y), h1 = __floats2half2_rn(a.z, a.w);
    half2 h2v = __floats2half2_rn(b.x, b.y), h3 = __floats2half2_rn(b.z, b.w);
    uint4 o;
    o.x = *(uint32_t*)&h0;  o.y = *(uint32_t*)&h1;
    o.z = *(uint32_t*)&h2v; o.w = *(uint32_t*)&h3;
    ((uint4*)d)[i] = o;
}

__global__ void cvt_ctx(const float* __restrict__ xc, const float* __restrict__ Wc){
    const size_t nA = (size_t)NN*DD/8, nB = (size_t)CC*DD/8;
    size_t i = (size_t)blockIdx.x * blockDim.x + threadIdx.x;
    if (i < nA) cvt8(xc, g_cxh, i);
    else if (i < nA + nB) cvt8(Wc, g_Wch, i - nA);
}

__global__ void cvt_rest(const float* __restrict__ x, const float* __restrict__ W1,
                         const float* __restrict__ W2, const float* __restrict__ cls){
    const size_t nA = (size_t)NN*DD/8, nB = (size_t)DD*DD/8, nC = (size_t)CC*DD/8;
    size_t i = (size_t)blockIdx.x * blockDim.x + threadIdx.x;
    if (i < nA) { cvt8(x, g_xh, i); return; }
    i -= nA;
    if (i < nB) { cvt8(W1, g_W1h, i); return; }
    i -= nB;
    if (i < nC) { cvt8(W2, g_W2h, i); return; }
    i -= nC;
    if (i < nC) cvt8(cls, g_Kh, i);
}

// ===================== small kernels =====================
__global__ void gate_gemv(const float* __restrict__ x, const float* __restrict__ Wg,
                          const float* __restrict__ bg){
    __shared__ float4 wsm[DD/4];
    int t = threadIdx.x;
    for (int j = t; j < DD/4; j += 256) wsm[j] = ((const float4*)Wg)[j];
    __syncthreads();
    int row = blockIdx.x * 8 + (t >> 5);
    int lane = t & 31;
    const float4* xr = (const float4*)(x + (size_t)row * DD);
    float s = 0.f;
    #pragma unroll
    for (int j = 0; j < 6; j++) {
        float4 a = xr[lane + j*32], b = wsm[lane + j*32];
        s += a.x*b.x + a.y*b.y + a.z*b.z + a.w*b.w;
    }
    #pragma unroll
    for (int o = 16; o; o >>= 1) s += __shfl_xor_sync(0xffffffffu, s, o);
    if (lane == 0) g_gate[row] = 0.5f / (1.f + expf(-(s + bg[0])));
}

__device__ __forceinline__ float block_sum(float v, float* red){
    int t = threadIdx.x;
    #pragma unroll
    for (int o = 16; o; o >>= 1) v += __shfl_xor_sync(0xffffffffu, v, o);
    if ((t & 31) == 0) red[t >> 5] = v;
    __syncthreads();
    if (t < 32) {
        float s = (t < (int)(blockDim.x >> 5)) ? red[t] : 0.f;
        #pragma unroll
        for (int o = 16; o; o >>= 1) s += __shfl_xor_sync(0xffffffffu, s, o);
        if (t == 0) red[0] = s;
    }
    __syncthreads();
    float r = red[0];
    __syncthreads();
    return r;
}
__device__ __forceinline__ float block_max(float v, float* red){
    int t = threadIdx.x;
    #pragma unroll
    for (int o = 16; o; o >>= 1) v = fmaxf(v, __shfl_xor_sync(0xffffffffu, v, o));
    if ((t & 31) == 0) red[t >> 5] = v;
    __syncthreads();
    if (t < 32) {
        float s = (t < (int)(blockDim.x >> 5)) ? red[t] : -3.0e38f;
        #pragma unroll
        for (int o = 16; o; o >>= 1) s = fmaxf(s, __shfl_xor_sync(0xffffffffu, s, o));
        if (t == 0) red[0] = s;
    }
    __syncthreads();
    float r = red[0];
    __syncthreads();
    return r;
}

__global__ void seg_accum(const float* __restrict__ x, const int* __restrict__ labels){
    int i = blockIdx.x;
    int lab = labels[i];
    if (lab < 1) return;
    int c = lab - 1;
    int t = threadIdx.x;
    float4 v = ((const float4*)(x + (size_t)i * DD))[t];
    float* s = g_sums + (size_t)c * DD + 4 * t;
    asm volatile("red.global.add.v4.f32 [%0], {%1,%2,%3,%4};"
        :: "l"(s), "f"(v.x), "f"(v.y), "f"(v.z), "f"(v.w) : "memory");
    if (t == 0) atomicAdd(&g_cnts[c], 1.0f);
}

__global__ void compute_vt(const float* __restrict__ hist, const int* __restrict__ hcnt){
    int c = blockIdx.x;
    if (c == CC - 1) {
        for (int d = threadIdx.x; d < DD; d += blockDim.x)
            g_vth[(size_t)d * CC] = __float2half(0.f);
        return;
    }
    float cnt = g_cnts[c];
    bool has = cnt > 0.f;
    int nc = hcnt[c] + (has ? 1 : 0);
    if (nc < 1) nc = 1;
    float scale = (1.f - MUF) / (1.f - powf(MUF, (float)nc));
    float inv_cnt = has ? (1.f / cnt) : 0.f;
    for (int d = threadIdx.x; d < DD; d += blockDim.x) {
        float hv = hist[(size_t)c * DD + d];
        float nh = has ? (MUF * hv + g_sums[(size_t)c * DD + d] * inv_cnt) : hv;
        g_vth[(size_t)d * CC + (c + 1)] = __float2half(nh * scale);
    }
}

__global__ void loss_fuse(const half* __restrict__ CTXH, half* __restrict__ WLH,
                          const int* __restrict__ labels){
    __shared__ float red[32];
    int t = threadIdx.x, i = blockIdx.x;
    const half2* cr = (const half2*)(CTXH + (size_t)i * CC);
    half2* wr = (half2*)(WLH + (size_t)i * CC);
    int lab = labels[i];
    half2 c0 = cr[2*t], c1 = cr[2*t+1];
    half2 w0 = wr[2*t], w1 = wr[2*t+1];
    float vc[4] = {__half2float(c0.x), __half2float(c0.y), __half2float(c1.x), __half2float(c1.y)};
    float vb[4] = {__half2float(w0.x), __half2float(w0.y), __half2float(w1.x), __half2float(w1.y)};
    float mc = fmaxf(fmaxf(vc[0], vc[1]), fmaxf(vc[2], vc[3]));
    float mb = fmaxf(fmaxf(vb[0], vb[1]), fmaxf(vb[2], vb[3]));
    if (lab >= 0) {
        float ms = 0.f;
        #pragma unroll
        for (int j = 0; j < 4; j++) { float d = vc[j] - vb[j]; ms += d * d; }
        ms = block_sum(ms, red);
        if (t == 0) atomicAdd(&g_acc[2], ms);
    }
    mc = block_max(mc, red);
    float sc = 0.f;
    #pragma unroll
    for (int j = 0; j < 4; j++) sc += expf(vc[j] - mc);
    sc = block_sum(sc, red);
    if (t == 0 && lab >= 0) {
        atomicAdd(&g_acc[1], (logf(sc) + mc) - __half2float(CTXH[(size_t)i * CC + lab]));
        atomicAdd(&g_acc[3], 1.0f);
    }
    mb = block_max(mb, red);
    float sb = 0.f;
    #pragma unroll
    for (int j = 0; j < 4; j++) { vb[j] = expf(vb[j] - mb); sb += vb[j]; }
    sb = block_sum(sb, red);
    float inv = 1.0f / sb;
    wr[2*t]   = __floats2half2_rn(vb[0]*inv, vb[1]*inv);
    wr[2*t+1] = __floats2half2_rn(vb[2]*inv, vb[3]*inv);
}

// scalar loads: logits pointer may be only 4B-aligned
__global__ void ce_rows(const float* __restrict__ L, const int* __restrict__ labels){
    __shared__ float red[32];
    int t = threadIdx.x, i = blockIdx.x;
    const float* row = L + (size_t)i * CC;
    float v[4];
    v[0] = row[4*t]; v[1] = row[4*t+1]; v[2] = row[4*t+2]; v[3] = row[4*t+3];
    float mx = fmaxf(fmaxf(v[0], v[1]), fmaxf(v[2], v[3]));
    mx = block_max(mx, red);
    float s = 0.f;
    #pragma unroll
    for (int j = 0; j < 4; j++) s += expf(v[j] - mx);
    s = block_sum(s, red);
    if (t == 0) {
        int lab = labels[i];
        if (lab >= 0) atomicAdd(&g_acc[0], (logf(s) + mx) - row[lab]);
    }
}

__global__ void finalize(float* __restrict__ out_loss){
    float nv = fmaxf(g_acc[3], 1.0f);
    out_loss[0] = g_acc[0] / nv + g_acc[1] / nv + LAMF * g_acc[2] / (nv * (float)CC);
}

// ===================== HMMA fp16 GEMM, CTA 128x256, warp tile 64x64 ========
// 8 warps (2x4), BK=64, 3-stage ring (48KB/stage), 1 CTA/SM.
// EPI: 0 f32 float2; 2 bias+gelu->fp16; 3 f32 scalar; 4 gate-mix->fp16; 5 bias->fp16.
#define STAGE_B 49152
#define GSMEM (3 * STAGE_B)

__device__ __forceinline__ void issue_stage(
    uint32_t base, const half* __restrict__ A, const half* __restrict__ B,
    int K, int rowA0, int rowB0, int kt, int t)
{
    #pragma unroll
    for (int i = 0; i < 12; i++) {
        int idx = t + i * 256;
        int ch = idx & 7;
        if (idx < 1024) {
            int row = idx >> 3;
            uint32_t off = (uint32_t)row * 128u + (uint32_t)((ch ^ (row & 7)) << 4);
            CPA16(base + off, (const void*)(A + (size_t)(rowA0 + row) * K + kt + ch * 8));
        } else {
            int rr = (idx >> 3) - 128;
            uint32_t off = (uint32_t)rr * 128u + (uint32_t)((ch ^ (rr & 7)) << 4);
            CPA16(base + 16384u + off, (const void*)(B + (size_t)(rowB0 + rr) * K + kt + ch * 8));
        }
    }
    CPCOMMIT();
}

template <int EPI>
__global__ void __launch_bounds__(256, 1) gemm_hmma(
    const half* __restrict__ A, const half* __restrict__ B,
    const float* __restrict__ bias, float* __restrict__ Cout,
    half* __restrict__ Oh, const half* __restrict__ Xh,
    int M, int K)
{
    extern __shared__ char smem[];
    uint32_t sb = smem_u32(smem);
    const int t = threadIdx.x;
    const int wid = t >> 5, lane = t & 31;
    const int wm = (wid & 1) * 64;
    const int wn = (wid >> 1) * 64;
    const int grp = lane >> 3, lrow = lane & 7;
    const int rowA0 = blockIdx.y * 128, rowB0 = blockIdx.x * 256;
    const int S = K / 64;

    uint32_t aoff[4], boff[4];
    #pragma unroll
    for (int mf = 0; mf < 4; mf++) {
        int row = wm + mf * 16 + (grp & 1) * 8 + lrow;
        int cb  = grp >> 1;
        aoff[mf] = (uint32_t)row * 128u + (uint32_t)((cb ^ (row & 7)) << 4);
    }
    #pragma unroll
    for (int np = 0; np < 4; np++) {
        int row = wn + np * 16 + (grp >> 1) * 8 + lrow;
        int cb  = grp & 1;
        boff[np] = 16384u + (uint32_t)row * 128u + (uint32_t)((cb ^ (row & 7)) << 4);
    }

    float acc[4][8][4];
    #pragma unroll
    for (int i = 0; i < 4; i++)
        #pragma unroll
        for (int j = 0; j < 8; j++)
            #pragma unroll
            for (int q = 0; q < 4; q++) acc[i][j][q] = 0.f;

    issue_stage(sb,             A, B, K, rowA0, rowB0, 0,   t);
    issue_stage(sb + STAGE_B,   A, B, K, rowA0, rowB0, 64,  t);
    issue_stage(sb + 2*STAGE_B, A, B, K, rowA0, rowB0, 128, t);

    uint32_t stb  = sb;
    uint32_t rstb = sb + 2*STAGE_B;
    for (int s = 0; s < S; s++) {
        CPWAIT(1);
        __syncthreads();
        if (s >= 1) {
            if (s + 2 < S) issue_stage(rstb, A, B, K, rowA0, rowB0, (s + 2) * 64, t);
            else CPCOMMIT();
        }

        #pragma unroll
        for (int kh = 0; kh < 4; kh++) {
            uint32_t kx = (uint32_t)kh << 5;
            uint32_t ah[4][4], bh[16];
            #pragma unroll
            for (int mf = 0; mf < 4; mf++) ldsm4(ah[mf], stb + (aoff[mf] ^ kx));
            #pragma unroll
            for (int np = 0; np < 4; np++) ldsm4(&bh[np*4], stb + (boff[np] ^ kx));
            #pragma unroll
            for (int mf = 0; mf < 4; mf++)
                #pragma unroll
                for (int nf = 0; nf < 8; nf++)
                    mma_fp16(acc[mf][nf], ah[mf], bh[nf*2], bh[nf*2+1]);
        }
        rstb = stb;
        stb += STAGE_B;
        if (stb == sb + 3*STAGE_B) stb = sb;
    }

    const int r0 = rowA0 + wm + (lane >> 2);
    const int cbase = rowB0 + wn + (lane & 3) * 2;
    #pragma unroll
    for (int mf = 0; mf < 4; mf++) {
        #pragma unroll
        for (int nf = 0; nf < 8; nf++) {
            int col = cbase + nf * 8;
            float b0 = 0.f, b1 = 0.f;
            if (EPI == 2 || EPI == 5) { b0 = bias[col]; b1 = bias[col + 1]; }
            #pragma unroll
            for (int half_i = 0; half_i < 2; half_i++) {
                int row = r0 + mf * 16 + half_i * 8;
                float v0 = acc[mf][nf][half_i*2]   + b0;
                float v1 = acc[mf][nf][half_i*2+1] + b1;
                if (EPI == 2) {
                    v0 = 0.5f * v0 * (1.0f + erff(v0 * 0.70710678118654752f));
                    v1 = 0.5f * v1 * (1.0f + erff(v1 * 0.70710678118654752f));
                    *(half2*)(Oh + (size_t)row * M + col) = __floats2half2_rn(v0, v1);
                } else if (EPI == 5) {
                    *(half2*)(Oh + (size_t)row * M + col) = __floats2half2_rn(v0, v1);
                } else if (EPI == 4) {
                    float g = bias[row];
                    size_t o = (size_t)row * M + col;
                    half2 xv = *(const half2*)(Xh + o);
                    float u0 = g * __half2float(xv.x) + (1.f - g) * v0;
                    float u1 = g * __half2float(xv.y) + (1.f - g) * v1;
                    *(half2*)(Oh + o) = __floats2half2_rn(u0, u1);
                } else if (EPI == 3) {
                    Cout[(size_t)row * M + col]     = v0;
                    Cout[(size_t)row * M + col + 1] = v1;
                } else {
                    *(float2*)(Cout + (size_t)row * M + col) = make_float2(v0, v1);
                }
            }
        }
    }
}

// ===================== launch =====================
#define SYM(p, s) cudaGetSymbolAddress((void**)&p, s)

extern "C" void kernel_launch(void* const* d_in, const int* in_sizes, int n_in,
                              void* d_out, int out_size) {
    const float* x          = (const float*)d_in[0];
    const float* x_ctx      = (const float*)d_in[1];
    const int*   labels     = (const int*)d_in[2];
    const float* classifier = (const float*)d_in[3];
    const float* W_ctx      = (const float*)d_in[4];
    const float* b_ctx      = (const float*)d_in[5];
    const float* W_g        = (const float*)d_in[6];
    const float* b_g        = (const float*)d_in[7];
    const float* W1         = (const float*)d_in[8];
    const float* b1         = (const float*)d_in[9];
    const float* W2         = (const float*)d_in[10];
    const float* b2         = (const float*)d_in[11];
    const float* hist       = (const float*)d_in[12];
    const int*   hcnt       = (const int*)d_in[13];

    cudaFuncSetAttribute(gemm_hmma<0>, cudaFuncAttributeMaxDynamicSharedMemorySize, GSMEM);
    cudaFuncSetAttribute(gemm_hmma<2>, cudaFuncAttributeMaxDynamicSharedMemorySize, GSMEM);
    cudaFuncSetAttribute(gemm_hmma<3>, cudaFuncAttributeMaxDynamicSharedMemorySize, GSMEM);
    cudaFuncSetAttribute(gemm_hmma<4>, cudaFuncAttributeMaxDynamicSharedMemorySize, GSMEM);
    cudaFuncSetAttribute(gemm_hmma<5>, cudaFuncAttributeMaxDynamicSharedMemorySize, GSMEM);

    float *p_red, *p_buf, *p_gate;
    half *p_xh,*p_cxh,*p_hh,*p_uh,*p_ctxh,*p_wlh,*p_vth,*p_Wch,*p_W1h,*p_W2h,*p_Kh;
    SYM(p_red,g_red);   SYM(p_buf,g_buf);   SYM(p_gate,g_gate);
    SYM(p_xh,g_xh);     SYM(p_cxh,g_cxh);   SYM(p_hh,g_hh);  SYM(p_uh,g_uh);
    SYM(p_ctxh,g_ctxh); SYM(p_wlh,g_wlh);   SYM(p_vth,g_vth);
    SYM(p_Wch,g_Wch);   SYM(p_W1h,g_W1h);   SYM(p_W2h,g_W2h); SYM(p_Kh,g_Kh);

    const bool fork = g_ss.ok;
    cudaStream_t sB = fork ? g_ss.s : (cudaStream_t)0;

    cudaMemsetAsync(p_red, 0, sizeof(float) * ((size_t)(CC-1)*DD + (CC-1) + 8));
    if (fork) {
        cudaEventRecord(g_ss.fork, 0);
        cudaStreamWaitEvent(sB, g_ss.fork, 0);
    }

    // side chain B: history + gate + remaining converts (hidden under gemm_ctx)
    seg_accum<<<NN, 192, 0, sB>>>(x, labels);
    compute_vt<<<CC, 256, 0, sB>>>(hist, hcnt);
    gate_gemv<<<NN/8, 256, 0, sB>>>(x, W_g, b_g);
    {
        size_t n8 = (size_t)NN*DD/8 + (size_t)DD*DD/8 + 2*(size_t)CC*DD/8;
        cvt_rest<<<(unsigned)((n8 + 255)/256), 256, 0, sB>>>(x, W1, W2, classifier);
    }
    if (fork) cudaEventRecord(g_ss.join, sB);

    // main chain: ctx converts then ctx GEMM
    {
        size_t n8 = (size_t)NN*DD/8 + (size_t)CC*DD/8;
        cvt_ctx<<<(unsigned)((n8 + 255)/256), 256>>>(x_ctx, W_ctx);
    }

    dim3 gNC(CC / 256, NN / 128);   // (4, 256)
    dim3 gND(DD / 256, NN / 128);   // (3, 256)

    gemm_hmma<5><<<gNC, 256, GSMEM>>>(p_cxh, p_Wch, b_ctx, 0, p_ctxh, 0, CC, DD);

    if (fork) cudaStreamWaitEvent(0, g_ss.join, 0);

    gemm_hmma<2><<<gND, 256, GSMEM>>>(p_xh, p_W1h, b1, 0, p_hh, 0, DD, DD);
    gemm_hmma<5><<<gNC, 256, GSMEM>>>(p_hh, p_W2h, b2, 0, p_wlh, 0, CC, DD);
    loss_fuse<<<NN, 256>>>(p_ctxh, p_wlh, labels);

    gemm_hmma<4><<<gND, 256, GSMEM>>>(p_wlh, p_vth, p_gate, 0, p_uh, p_xh, DD, CC);

    float* outF = (float*)d_out;
    size_t NCt = (size_t)NN * CC;
    if ((size_t)out_size >= NCt + 1) {
        float* logits = outF + ((size_t)out_size - NCt);
        if ((((uintptr_t)logits) & 7) == 0)
            gemm_hmma<0><<<gNC, 256, GSMEM>>>(p_uh, p_Kh, 0, logits, 0, 0, CC, DD);
        else
            gemm_hmma<3><<<gNC, 256, GSMEM>>>(p_uh, p_Kh, 0, logits, 0, 0, CC, DD);
        ce_rows<<<NN, 256>>>(logits, labels);
        finalize<<<1, 1>>>(outF);
    } else if ((size_t)out_size == NCt) {
        gemm_hmma<0><<<gNC, 256, GSMEM>>>(p_uh, p_Kh, 0, outF, 0, 0, CC, DD);
        ce_rows<<<NN, 256>>>(outF, labels);
    } else {
        gemm_hmma<0><<<gNC, 256, GSMEM>>>(p_uh, p_Kh, 0, p_buf, 0, 0, CC, DD);
        ce_rows<<<NN, 256>>>(p_buf, labels);
        finalize<<<1, 1>>>(outF);
    }
}

// round 15
// speedup vs baseline: 1.0538x; 1.0538x over previous
#include <cuda_runtime.h>
#include <cuda_fp16.h>
#include <math.h>
#include <stdint.h>

#define NN 32768
#define DD 768
#define CC 1024
#define MUF 0.9f
#define LAMF 0.5f

// ===================== PTX helpers =====================
__device__ __forceinline__ uint32_t smem_u32(const void* p){
    uint32_t a;
    asm("{ .reg .u64 t; cvta.to.shared.u64 t, %1; cvt.u32.u64 %0, t; }" : "=r"(a) : "l"(p));
    return a;
}
#define CPA16(d,s)  asm volatile("cp.async.cg.shared.global [%0], [%1], 16;"::"r"(d),"l"(s))
#define CPCOMMIT()  asm volatile("cp.async.commit_group;":::"memory")
#define CPWAIT(n)   asm volatile("cp.async.wait_group %0;"::"n"(n):"memory")

__device__ __forceinline__ void ldsm4(uint32_t* r, uint32_t addr){
    asm volatile("ldmatrix.sync.aligned.m8n8.x4.shared.b16 {%0,%1,%2,%3}, [%4];"
        : "=r"(r[0]), "=r"(r[1]), "=r"(r[2]), "=r"(r[3]) : "r"(addr));
}
__device__ __forceinline__ void mma_fp16(float* c, const uint32_t* a, uint32_t b0, uint32_t b1){
    asm volatile(
        "mma.sync.aligned.m16n8k16.row.col.f32.f16.f16.f32 "
        "{%0,%1,%2,%3}, {%4,%5,%6,%7}, {%8,%9}, {%0,%1,%2,%3};"
        : "+f"(c[0]), "+f"(c[1]), "+f"(c[2]), "+f"(c[3])
        : "r"(a[0]), "r"(a[1]), "r"(a[2]), "r"(a[3]), "r"(b0), "r"(b1));
}

// ===================== scratch =====================
__device__ half g_xh[(size_t)NN*DD];
__device__ half g_cxh[(size_t)NN*DD + (size_t)NN*(CC-DD)];  // x_ctx fp16, later reused for w (NN*CC)
__device__ half g_hh[(size_t)NN*DD];
__device__ half g_uh[(size_t)NN*DD];
__device__ half g_ctxh[(size_t)NN*CC];
__device__ half g_wlh[(size_t)NN*CC];
__device__ half g_vth[DD*CC];
__device__ half g_Wch[CC*DD];
__device__ half g_W1h[DD*DD];
__device__ half g_W2h[CC*DD];
__device__ half g_Kh[CC*DD];
__device__ float g_buf[(size_t)NN*CC];
__device__ float g_gate[NN];
__device__ float g_red[(size_t)(CC-1)*DD + (CC-1) + 8];
#define g_sums (g_red)
#define g_cnts (g_red + (size_t)(CC-1)*DD)
#define g_acc  (g_red + (size_t)(CC-1)*DD + (CC-1))

// ===================== side stream =====================
struct SideStream {
    cudaStream_t s = 0;
    cudaEvent_t fork = 0, join = 0, fork2 = 0, join2 = 0;
    bool ok = false;
    SideStream(){
        if (cudaStreamCreateWithFlags(&s, cudaStreamNonBlocking) == cudaSuccess &&
            cudaEventCreateWithFlags(&fork,  cudaEventDisableTiming) == cudaSuccess &&
            cudaEventCreateWithFlags(&join,  cudaEventDisableTiming) == cudaSuccess &&
            cudaEventCreateWithFlags(&fork2, cudaEventDisableTiming) == cudaSuccess &&
            cudaEventCreateWithFlags(&join2, cudaEventDisableTiming) == cudaSuccess)
            ok = true;
    }
};
static SideStream g_ss;

// ===================== cvt kernels =====================
__device__ __forceinline__ void cvt8(const float* __restrict__ s,
                                     half* __restrict__ d, size_t i){
    float4 a = ((const float4*)s)[2*i], b = ((const float4*)s)[2*i+1];
    half2 h0 = __floats2half2_rn(a.x, a.y), h1 = __floats2half2_rn(a.z, a.w);
    half2 h2v = __floats2half2_rn(b.x, b.y), h3 = __floats2half2_rn(b.z, b.w);
    uint4 o;
    o.x = *(uint32_t*)&h0;  o.y = *(uint32_t*)&h1;
    o.z = *(uint32_t*)&h2v; o.w = *(uint32_t*)&h3;
    ((uint4*)d)[i] = o;
}

__global__ void cvt_ctx(const float* __restrict__ xc, const float* __restrict__ Wc){
    const size_t nA = (size_t)NN*DD/8, nB = (size_t)CC*DD/8;
    size_t i = (size_t)blockIdx.x * blockDim.x + threadIdx.x;
    if (i < nA) cvt8(xc, g_cxh, i);
    else if (i < nA + nB) cvt8(Wc, g_Wch, i - nA);
}

__global__ void cvt_rest(const float* __restrict__ x, const float* __restrict__ W1,
                         const float* __restrict__ W2, const float* __restrict__ cls){
    const size_t nA = (size_t)NN*DD/8, nB = (size_t)DD*DD/8, nC = (size_t)CC*DD/8;
    size_t i = (size_t)blockIdx.x * blockDim.x + threadIdx.x;
    if (i < nA) { cvt8(x, g_xh, i); return; }
    i -= nA;
    if (i < nB) { cvt8(W1, g_W1h, i); return; }
    i -= nB;
    if (i < nC) { cvt8(W2, g_W2h, i); return; }
    i -= nC;
    if (i < nC) cvt8(cls, g_Kh, i);
}

// ===================== small kernels =====================
__global__ void gate_gemv(const float* __restrict__ x, const float* __restrict__ Wg,
                          const float* __restrict__ bg){
    __shared__ float4 wsm[DD/4];
    int t = threadIdx.x;
    for (int j = t; j < DD/4; j += 256) wsm[j] = ((const float4*)Wg)[j];
    __syncthreads();
    int row = blockIdx.x * 8 + (t >> 5);
    int lane = t & 31;
    const float4* xr = (const float4*)(x + (size_t)row * DD);
    float s = 0.f;
    #pragma unroll
    for (int j = 0; j < 6; j++) {
        float4 a = xr[lane + j*32], b = wsm[lane + j*32];
        s += a.x*b.x + a.y*b.y + a.z*b.z + a.w*b.w;
    }
    #pragma unroll
    for (int o = 16; o; o >>= 1) s += __shfl_xor_sync(0xffffffffu, s, o);
    if (lane == 0) g_gate[row] = 0.5f / (1.f + expf(-(s + bg[0])));
}

__device__ __forceinline__ float block_sum(float v, float* red){
    int t = threadIdx.x;
    #pragma unroll
    for (int o = 16; o; o >>= 1) v += __shfl_xor_sync(0xffffffffu, v, o);
    if ((t & 31) == 0) red[t >> 5] = v;
    __syncthreads();
    if (t < 32) {
        float s = (t < (int)(blockDim.x >> 5)) ? red[t] : 0.f;
        #pragma unroll
        for (int o = 16; o; o >>= 1) s += __shfl_xor_sync(0xffffffffu, s, o);
        if (t == 0) red[0] = s;
    }
    __syncthreads();
    float r = red[0];
    __syncthreads();
    return r;
}
__device__ __forceinline__ float block_max(float v, float* red){
    int t = threadIdx.x;
    #pragma unroll
    for (int o = 16; o; o >>= 1) v = fmaxf(v, __shfl_xor_sync(0xffffffffu, v, o));
    if ((t & 31) == 0) red[t >> 5] = v;
    __syncthreads();
    if (t < 32) {
        float s = (t < (int)(blockDim.x >> 5)) ? red[t] : -3.0e38f;
        #pragma unroll
        for (int o = 16; o; o >>= 1) s = fmaxf(s, __shfl_xor_sync(0xffffffffu, s, o));
        if (t == 0) red[0] = s;
    }
    __syncthreads();
    float r = red[0];
    __syncthreads();
    return r;
}

__global__ void seg_accum(const float* __restrict__ x, const int* __restrict__ labels){
    int i = blockIdx.x;
    int lab = labels[i];
    if (lab < 1) return;
    int c = lab - 1;
    int t = threadIdx.x;
    float4 v = ((const float4*)(x + (size_t)i * DD))[t];
    float* s = g_sums + (size_t)c * DD + 4 * t;
    asm volatile("red.global.add.v4.f32 [%0], {%1,%2,%3,%4};"
        :: "l"(s), "f"(v.x), "f"(v.y), "f"(v.z), "f"(v.w) : "memory");
    if (t == 0) atomicAdd(&g_cnts[c], 1.0f);
}

__global__ void compute_vt(const float* __restrict__ hist, const int* __restrict__ hcnt){
    int c = blockIdx.x;
    if (c == CC - 1) {
        for (int d = threadIdx.x; d < DD; d += blockDim.x)
            g_vth[(size_t)d * CC] = __float2half(0.f);
        return;
    }
    float cnt = g_cnts[c];
    bool has = cnt > 0.f;
    int nc = hcnt[c] + (has ? 1 : 0);
    if (nc < 1) nc = 1;
    float scale = (1.f - MUF) / (1.f - powf(MUF, (float)nc));
    float inv_cnt = has ? (1.f / cnt) : 0.f;
    for (int d = threadIdx.x; d < DD; d += blockDim.x) {
        float hv = hist[(size_t)c * DD + d];
        float nh = has ? (MUF * hv + g_sums[(size_t)c * DD + d] * inv_cnt) : hv;
        g_vth[(size_t)d * CC + (c + 1)] = __float2half(nh * scale);
    }
}

// softmax(w_logits) -> w into g_cxh (x_ctx fp16 is dead by now)
__global__ void softmax_w(const half* __restrict__ WLH, half* __restrict__ Wout){
    __shared__ float red[32];
    int t = threadIdx.x, i = blockIdx.x;
    const half2* wr = (const half2*)(WLH + (size_t)i * CC);
    half2 w0 = wr[2*t], w1 = wr[2*t+1];
    float vb[4] = {__half2float(w0.x), __half2float(w0.y), __half2float(w1.x), __half2float(w1.y)};
    float mb = fmaxf(fmaxf(vb[0], vb[1]), fmaxf(vb[2], vb[3]));
    mb = block_max(mb, red);
    float sb = 0.f;
    #pragma unroll
    for (int j = 0; j < 4; j++) { vb[j] = expf(vb[j] - mb); sb += vb[j]; }
    sb = block_sum(sb, red);
    float inv = 1.0f / sb;
    half2* wo = (half2*)(Wout + (size_t)i * CC);
    wo[2*t]   = __floats2half2_rn(vb[0]*inv, vb[1]*inv);
    wo[2*t+1] = __floats2half2_rn(vb[2]*inv, vb[3]*inv);
}

// CE(ctx) + masked MSE (side stream, overlaps gemm_sub/gemm_logits)
__global__ void ce_ctx_mse(const half* __restrict__ CTXH, const half* __restrict__ WLH,
                           const int* __restrict__ labels){
    __shared__ float red[32];
    int t = threadIdx.x, i = blockIdx.x;
    int lab = labels[i];
    const half2* cr = (const half2*)(CTXH + (size_t)i * CC);
    const half2* wr = (const half2*)(WLH + (size_t)i * CC);
    half2 c0 = cr[2*t], c1 = cr[2*t+1];
    half2 w0 = wr[2*t], w1 = wr[2*t+1];
    float vc[4] = {__half2float(c0.x), __half2float(c0.y), __half2float(c1.x), __half2float(c1.y)};
    float vb[4] = {__half2float(w0.x), __half2float(w0.y), __half2float(w1.x), __half2float(w1.y)};
    if (lab >= 0) {
        float ms = 0.f;
        #pragma unroll
        for (int j = 0; j < 4; j++) { float d = vc[j] - vb[j]; ms += d * d; }
        ms = block_sum(ms, red);
        if (t == 0) atomicAdd(&g_acc[2], ms);
    }
    float mc = fmaxf(fmaxf(vc[0], vc[1]), fmaxf(vc[2], vc[3]));
    mc = block_max(mc, red);
    float sc = 0.f;
    #pragma unroll
    for (int j = 0; j < 4; j++) sc += expf(vc[j] - mc);
    sc = block_sum(sc, red);
    if (t == 0 && lab >= 0) {
        atomicAdd(&g_acc[1], (logf(sc) + mc) - __half2float(CTXH[(size_t)i * CC + lab]));
        atomicAdd(&g_acc[3], 1.0f);
    }
}

// scalar loads: logits pointer may be only 4B-aligned
__global__ void ce_rows(const float* __restrict__ L, const int* __restrict__ labels){
    __shared__ float red[32];
    int t = threadIdx.x, i = blockIdx.x;
    const float* row = L + (size_t)i * CC;
    float v[4];
    v[0] = row[4*t]; v[1] = row[4*t+1]; v[2] = row[4*t+2]; v[3] = row[4*t+3];
    float mx = fmaxf(fmaxf(v[0], v[1]), fmaxf(v[2], v[3]));
    mx = block_max(mx, red);
    float s = 0.f;
    #pragma unroll
    for (int j = 0; j < 4; j++) s += expf(v[j] - mx);
    s = block_sum(s, red);
    if (t == 0) {
        int lab = labels[i];
        if (lab >= 0) atomicAdd(&g_acc[0], (logf(s) + mx) - row[lab]);
    }
}

__global__ void finalize(float* __restrict__ out_loss){
    float nv = fmaxf(g_acc[3], 1.0f);
    out_loss[0] = g_acc[0] / nv + g_acc[1] / nv + LAMF * g_acc[2] / (nv * (float)CC);
}

// ===================== HMMA fp16 GEMM (R13 config: 128x128, 64x32 warp) ====
#define STAGE_B 32768
#define GSMEM (3 * STAGE_B)

__device__ __forceinline__ void issue_stage(
    uint32_t base, const half* __restrict__ A, const half* __restrict__ B,
    int K, int rowA0, int rowB0, int kt, int t)
{
    #pragma unroll
    for (int i = 0; i < 4; i++) {
        int idx = t + i * 256;
        int row = idx >> 3, ch = idx & 7;
        uint32_t off = (uint32_t)row * 128u + (uint32_t)((ch ^ (row & 7)) << 4);
        CPA16(base + off,           (const void*)(A + (size_t)(rowA0 + row) * K + kt + ch * 8));
        CPA16(base + 16384u + off,  (const void*)(B + (size_t)(rowB0 + row) * K + kt + ch * 8));
    }
    CPCOMMIT();
}

template <int EPI>
__global__ void __launch_bounds__(256, 2) gemm_hmma(
    const half* __restrict__ A, const half* __restrict__ B,
    const float* __restrict__ bias, float* __restrict__ Cout,
    half* __restrict__ Oh, const half* __restrict__ Xh,
    int M, int K)
{
    extern __shared__ char smem[];
    uint32_t sb = smem_u32(smem);
    const int t = threadIdx.x;
    const int wid = t >> 5, lane = t & 31;
    const int wm = (wid & 1) * 64;
    const int wn = (wid >> 1) * 32;
    const int grp = lane >> 3, lrow = lane & 7;
    const int rowA0 = blockIdx.y * 128, rowB0 = blockIdx.x * 128;
    const int S = K / 64;

    uint32_t aoff[4], boff[2];
    #pragma unroll
    for (int mf = 0; mf < 4; mf++) {
        int row = wm + mf * 16 + (grp & 1) * 8 + lrow;
        int cb  = grp >> 1;
        aoff[mf] = (uint32_t)row * 128u + (uint32_t)((cb ^ (row & 7)) << 4);
    }
    #pragma unroll
    for (int np = 0; np < 2; np++) {
        int row = wn + np * 16 + (grp >> 1) * 8 + lrow;
        int cb  = grp & 1;
        boff[np] = 16384u + (uint32_t)row * 128u + (uint32_t)((cb ^ (row & 7)) << 4);
    }

    float acc[4][4][4];
    #pragma unroll
    for (int i = 0; i < 4; i++)
        #pragma unroll
        for (int j = 0; j < 4; j++)
            #pragma unroll
            for (int q = 0; q < 4; q++) acc[i][j][q] = 0.f;

    issue_stage(sb,             A, B, K, rowA0, rowB0, 0,   t);
    issue_stage(sb + STAGE_B,   A, B, K, rowA0, rowB0, 64,  t);
    issue_stage(sb + 2*STAGE_B, A, B, K, rowA0, rowB0, 128, t);

    uint32_t stb  = sb;
    uint32_t rstb = sb + 2*STAGE_B;
    for (int s = 0; s < S; s++) {
        CPWAIT(1);
        __syncthreads();
        if (s >= 1) {
            if (s + 2 < S) issue_stage(rstb, A, B, K, rowA0, rowB0, (s + 2) * 64, t);
            else CPCOMMIT();
        }

        uint32_t bh[2][8];
        ldsm4(&bh[0][0], stb + boff[0]);
        ldsm4(&bh[0][4], stb + boff[1]);
        #pragma unroll
        for (int kh = 0; kh < 4; kh++) {
            uint32_t kx = (uint32_t)kh << 5;
            uint32_t ah[4][4];
            #pragma unroll
            for (int mf = 0; mf < 4; mf++) ldsm4(ah[mf], stb + (aoff[mf] ^ kx));
            if (kh < 3) {
                uint32_t kx2 = (uint32_t)(kh + 1) << 5;
                ldsm4(&bh[(kh+1)&1][0], stb + (boff[0] ^ kx2));
                ldsm4(&bh[(kh+1)&1][4], stb + (boff[1] ^ kx2));
            }
            const uint32_t* bc = bh[kh & 1];
            #pragma unroll
            for (int mf = 0; mf < 4; mf++)
                #pragma unroll
                for (int nf = 0; nf < 4; nf++)
                    mma_fp16(acc[mf][nf], ah[mf], bc[nf*2], bc[nf*2+1]);
        }
        rstb = stb;
        stb += STAGE_B;
        if (stb == sb + 3*STAGE_B) stb = sb;
    }

    const int r0 = rowA0 + wm + (lane >> 2);
    const int cbase = rowB0 + wn + (lane & 3) * 2;
    #pragma unroll
    for (int mf = 0; mf < 4; mf++) {
        #pragma unroll
        for (int nf = 0; nf < 4; nf++) {
            int col = cbase + nf * 8;
            float b0 = 0.f, b1 = 0.f;
            if (EPI == 2 || EPI == 5) { b0 = bias[col]; b1 = bias[col + 1]; }
            #pragma unroll
            for (int half_i = 0; half_i < 2; half_i++) {
                int row = r0 + mf * 16 + half_i * 8;
                float v0 = acc[mf][nf][half_i*2]   + b0;
                float v1 = acc[mf][nf][half_i*2+1] + b1;
                if (EPI == 2) {
                    v0 = 0.5f * v0 * (1.0f + erff(v0 * 0.70710678118654752f));
                    v1 = 0.5f * v1 * (1.0f + erff(v1 * 0.70710678118654752f));
                    *(half2*)(Oh + (size_t)row * M + col) = __floats2half2_rn(v0, v1);
                } else if (EPI == 5) {
                    *(half2*)(Oh + (size_t)row * M + col) = __floats2half2_rn(v0, v1);
                } else if (EPI == 4) {
                    float g = bias[row];
                    size_t o = (size_t)row * M + col;
                    half2 xv = *(const half2*)(Xh + o);
                    float u0 = g * __half2float(xv.x) + (1.f - g) * v0;
                    float u1 = g * __half2float(xv.y) + (1.f - g) * v1;
                    *(half2*)(Oh + o) = __floats2half2_rn(u0, u1);
                } else if (EPI == 3) {
                    Cout[(size_t)row * M + col]     = v0;
                    Cout[(size_t)row * M + col + 1] = v1;
                } else {
                    *(float2*)(Cout + (size_t)row * M + col) = make_float2(v0, v1);
                }
            }
        }
    }
}

// ===================== launch =====================
#define SYM(p, s) cudaGetSymbolAddress((void**)&p, s)

extern "C" void kernel_launch(void* const* d_in, const int* in_sizes, int n_in,
                              void* d_out, int out_size) {
    const float* x          = (const float*)d_in[0];
    const float* x_ctx      = (const float*)d_in[1];
    const int*   labels     = (const int*)d_in[2];
    const float* classifier = (const float*)d_in[3];
    const float* W_ctx      = (const float*)d_in[4];
    const float* b_ctx      = (const float*)d_in[5];
    const float* W_g        = (const float*)d_in[6];
    const float* b_g        = (const float*)d_in[7];
    const float* W1         = (const float*)d_in[8];
    const float* b1         = (const float*)d_in[9];
    const float* W2         = (const float*)d_in[10];
    const float* b2         = (const float*)d_in[11];
    const float* hist       = (const float*)d_in[12];
    const int*   hcnt       = (const int*)d_in[13];

    cudaFuncSetAttribute(gemm_hmma<0>, cudaFuncAttributeMaxDynamicSharedMemorySize, GSMEM);
    cudaFuncSetAttribute(gemm_hmma<2>, cudaFuncAttributeMaxDynamicSharedMemorySize, GSMEM);
    cudaFuncSetAttribute(gemm_hmma<3>, cudaFuncAttributeMaxDynamicSharedMemorySize, GSMEM);
    cudaFuncSetAttribute(gemm_hmma<4>, cudaFuncAttributeMaxDynamicSharedMemorySize, GSMEM);
    cudaFuncSetAttribute(gemm_hmma<5>, cudaFuncAttributeMaxDynamicSharedMemorySize, GSMEM);

    float *p_red, *p_buf, *p_gate;
    half *p_xh,*p_cxh,*p_hh,*p_uh,*p_ctxh,*p_wlh,*p_vth,*p_Wch,*p_W1h,*p_W2h,*p_Kh;
    SYM(p_red,g_red);   SYM(p_buf,g_buf);   SYM(p_gate,g_gate);
    SYM(p_xh,g_xh);     SYM(p_cxh,g_cxh);   SYM(p_hh,g_hh);  SYM(p_uh,g_uh);
    SYM(p_ctxh,g_ctxh); SYM(p_wlh,g_wlh);   SYM(p_vth,g_vth);
    SYM(p_Wch,g_Wch);   SYM(p_W1h,g_W1h);   SYM(p_W2h,g_W2h); SYM(p_Kh,g_Kh);

    const bool fork = g_ss.ok;
    cudaStream_t sB = fork ? g_ss.s : (cudaStream_t)0;

    cudaMemsetAsync(p_red, 0, sizeof(float) * ((size_t)(CC-1)*DD + (CC-1) + 8));
    if (fork) {
        cudaEventRecord(g_ss.fork, 0);
        cudaStreamWaitEvent(sB, g_ss.fork, 0);
    }

    // side chain B: history + gate + remaining converts (hidden under gemm_ctx)
    seg_accum<<<NN, 192, 0, sB>>>(x, labels);
    compute_vt<<<CC, 256, 0, sB>>>(hist, hcnt);
    gate_gemv<<<NN/8, 256, 0, sB>>>(x, W_g, b_g);
    {
        size_t n8 = (size_t)NN*DD/8 + (size_t)DD*DD/8 + 2*(size_t)CC*DD/8;
        cvt_rest<<<(unsigned)((n8 + 255)/256), 256, 0, sB>>>(x, W1, W2, classifier);
    }
    if (fork) cudaEventRecord(g_ss.join, sB);

    // main chain: ctx converts then ctx GEMM
    {
        size_t n8 = (size_t)NN*DD/8 + (size_t)CC*DD/8;
        cvt_ctx<<<(unsigned)((n8 + 255)/256), 256>>>(x_ctx, W_ctx);
    }

    dim3 gNC(CC / 128, NN / 128);
    dim3 gND(DD / 128, NN / 128);

    gemm_hmma<5><<<gNC, 256, GSMEM>>>(p_cxh, p_Wch, b_ctx, 0, p_ctxh, 0, CC, DD);

    if (fork) cudaStreamWaitEvent(0, g_ss.join, 0);

    gemm_hmma<2><<<gND, 256, GSMEM>>>(p_xh, p_W1h, b1, 0, p_hh, 0, DD, DD);
    gemm_hmma<5><<<gNC, 256, GSMEM>>>(p_hh, p_W2h, b2, 0, p_wlh, 0, CC, DD);

    // fork CE(ctx)+MSE onto side stream (overlaps gemm_sub + gemm_logits)
    if (fork) {
        cudaEventRecord(g_ss.fork2, 0);
        cudaStreamWaitEvent(sB, g_ss.fork2, 0);
        ce_ctx_mse<<<NN, 256, 0, sB>>>(p_ctxh, p_wlh, labels);
        cudaEventRecord(g_ss.join2, sB);
    } else {
        ce_ctx_mse<<<NN, 256>>>(p_ctxh, p_wlh, labels);
    }

    // softmax -> w into g_cxh (dead buffer), then substitute+gate-mix GEMM
    softmax_w<<<NN, 256>>>(p_wlh, p_cxh);
    gemm_hmma<4><<<gND, 256, GSMEM>>>(p_cxh, p_vth, p_gate, 0, p_uh, p_xh, DD, CC);

    float* outF = (float*)d_out;
    size_t NCt = (size_t)NN * CC;
    if ((size_t)out_size >= NCt + 1) {
        float* logits = outF + ((size_t)out_size - NCt);
        if ((((uintptr_t)logits) & 7) == 0)
            gemm_hmma<0><<<gNC, 256, GSMEM>>>(p_uh, p_Kh, 0, logits, 0, 0, CC, DD);
        else
            gemm_hmma<3><<<gNC, 256, GSMEM>>>(p_uh, p_Kh, 0, logits, 0, 0, CC, DD);
        ce_rows<<<NN, 256>>>(logits, labels);
        if (fork) cudaStreamWaitEvent(0, g_ss.join2, 0);
        finalize<<<1, 1>>>(outF);
    } else if ((size_t)out_size == NCt) {
        gemm_hmma<0><<<gNC, 256, GSMEM>>>(p_uh, p_Kh, 0, outF, 0, 0, CC, DD);
        ce_rows<<<NN, 256>>>(outF, labels);
        if (fork) cudaStreamWaitEvent(0, g_ss.join2, 0);
    } else {
        gemm_hmma<0><<<gNC, 256, GSMEM>>>(p_uh, p_Kh, 0, p_buf, 0, 0, CC, DD);
        ce_rows<<<NN, 256>>>(p_buf, labels);
        if (fork) cudaStreamWaitEvent(0, g_ss.join2, 0);
        finalize<<<1, 1>>>(outF);
    }
}

// round 16
// speedup vs baseline: 1.1028x; 1.0465x over previous
#include <cuda_runtime.h>
#include <cuda_fp16.h>
#include <math.h>
#include <stdint.h>

#define NN 32768
#define DD 768
#define CC 1024
#define MUF 0.9f
#define LAMF 0.5f

// ===================== PTX helpers =====================
__device__ __forceinline__ uint32_t smem_u32(const void* p){
    uint32_t a;
    asm("{ .reg .u64 t; cvta.to.shared.u64 t, %1; cvt.u32.u64 %0, t; }" : "=r"(a) : "l"(p));
    return a;
}
#define CPA16(d,s)  asm volatile("cp.async.cg.shared.global [%0], [%1], 16;"::"r"(d),"l"(s))
#define CPCOMMIT()  asm volatile("cp.async.commit_group;":::"memory")
#define CPWAIT(n)   asm volatile("cp.async.wait_group %0;"::"n"(n):"memory")

__device__ __forceinline__ void ldsm4(uint32_t* r, uint32_t addr){
    asm volatile("ldmatrix.sync.aligned.m8n8.x4.shared.b16 {%0,%1,%2,%3}, [%4];"
        : "=r"(r[0]), "=r"(r[1]), "=r"(r[2]), "=r"(r[3]) : "r"(addr));
}
__device__ __forceinline__ void mma_fp16(float* c, const uint32_t* a, uint32_t b0, uint32_t b1){
    asm volatile(
        "mma.sync.aligned.m16n8k16.row.col.f32.f16.f16.f32 "
        "{%0,%1,%2,%3}, {%4,%5,%6,%7}, {%8,%9}, {%0,%1,%2,%3};"
        : "+f"(c[0]), "+f"(c[1]), "+f"(c[2]), "+f"(c[3])
        : "r"(a[0]), "r"(a[1]), "r"(a[2]), "r"(a[3]), "r"(b0), "r"(b1));
}

// ===================== scratch =====================
__device__ half g_xh[(size_t)NN*DD];
__device__ half g_cxh[(size_t)NN*DD];
__device__ half g_hh[(size_t)NN*DD];
__device__ half g_uh[(size_t)NN*DD];
__device__ half g_ctxh[(size_t)NN*CC];
__device__ half g_wlh[(size_t)NN*CC];
__device__ half g_vth[DD*CC];
__device__ half g_Wch[CC*DD];
__device__ half g_W1h[DD*DD];
__device__ half g_W2h[CC*DD];
__device__ half g_Kh[CC*DD];
__device__ float g_buf[(size_t)NN*CC];
__device__ float g_gate[NN];
__device__ float g_red[(size_t)(CC-1)*DD + (CC-1) + 8];
#define g_sums (g_red)
#define g_cnts (g_red + (size_t)(CC-1)*DD)
#define g_acc  (g_red + (size_t)(CC-1)*DD + (CC-1))

// ===================== side stream =====================
struct SideStream {
    cudaStream_t s = 0;
    cudaEvent_t fork = 0, join = 0;
    bool ok = false;
    SideStream(){
        if (cudaStreamCreateWithFlags(&s, cudaStreamNonBlocking) == cudaSuccess &&
            cudaEventCreateWithFlags(&fork, cudaEventDisableTiming) == cudaSuccess &&
            cudaEventCreateWithFlags(&join, cudaEventDisableTiming) == cudaSuccess)
            ok = true;
    }
};
static SideStream g_ss;

// ===================== cvt kernels =====================
__device__ __forceinline__ void cvt8(const float* __restrict__ s,
                                     half* __restrict__ d, size_t i){
    float4 a = ((const float4*)s)[2*i], b = ((const float4*)s)[2*i+1];
    half2 h0 = __floats2half2_rn(a.x, a.y), h1 = __floats2half2_rn(a.z, a.w);
    half2 h2v = __floats2half2_rn(b.x, b.y), h3 = __floats2half2_rn(b.z, b.w);
    uint4 o;
    o.x = *(uint32_t*)&h0;  o.y = *(uint32_t*)&h1;
    o.z = *(uint32_t*)&h2v; o.w = *(uint32_t*)&h3;
    ((uint4*)d)[i] = o;
}

__global__ void cvt_ctx(const float* __restrict__ xc, const float* __restrict__ Wc){
    const size_t nA = (size_t)NN*DD/8, nB = (size_t)CC*DD/8;
    size_t i = (size_t)blockIdx.x * blockDim.x + threadIdx.x;
    if (i < nA) cvt8(xc, g_cxh, i);
    else if (i < nA + nB) cvt8(Wc, g_Wch, i - nA);
}

__global__ void cvt_rest(const float* __restrict__ x, const float* __restrict__ W1,
                         const float* __restrict__ W2, const float* __restrict__ cls){
    const size_t nA = (size_t)NN*DD/8, nB = (size_t)DD*DD/8, nC = (size_t)CC*DD/8;
    size_t i = (size_t)blockIdx.x * blockDim.x + threadIdx.x;
    if (i < nA) { cvt8(x, g_xh, i); return; }
    i -= nA;
    if (i < nB) { cvt8(W1, g_W1h, i); return; }
    i -= nB;
    if (i < nC) { cvt8(W2, g_W2h, i); return; }
    i -= nC;
    if (i < nC) cvt8(cls, g_Kh, i);
}

// ===================== small kernels =====================
// g = sigmoid(x @ W_g + b_g)*0.5 ; reads fp16 xh (after cvt_rest, same stream)
__global__ void gate_gemv(const float* __restrict__ Wg, const float* __restrict__ bg){
    __shared__ float2 wsm[DD/2];
    int t = threadIdx.x;
    for (int j = t; j < DD/2; j += 256) wsm[j] = ((const float2*)Wg)[j];
    __syncthreads();
    int row = blockIdx.x * 8 + (t >> 5);
    int lane = t & 31;
    const half2* xr = (const half2*)(g_xh + (size_t)row * DD);
    float s = 0.f;
    #pragma unroll
    for (int j = 0; j < 12; j++) {
        half2 a = xr[lane + j*32];
        float2 b = wsm[lane + j*32];
        s += __half2float(a.x)*b.x + __half2float(a.y)*b.y;
    }
    #pragma unroll
    for (int o = 16; o; o >>= 1) s += __shfl_xor_sync(0xffffffffu, s, o);
    if (lane == 0) g_gate[row] = 0.5f / (1.f + expf(-(s + bg[0])));
}

__device__ __forceinline__ float block_sum(float v, float* red){
    int t = threadIdx.x;
    #pragma unroll
    for (int o = 16; o; o >>= 1) v += __shfl_xor_sync(0xffffffffu, v, o);
    if ((t & 31) == 0) red[t >> 5] = v;
    __syncthreads();
    if (t < 32) {
        float s = (t < (int)(blockDim.x >> 5)) ? red[t] : 0.f;
        #pragma unroll
        for (int o = 16; o; o >>= 1) s += __shfl_xor_sync(0xffffffffu, s, o);
        if (t == 0) red[0] = s;
    }
    __syncthreads();
    float r = red[0];
    __syncthreads();
    return r;
}
__device__ __forceinline__ float block_max(float v, float* red){
    int t = threadIdx.x;
    #pragma unroll
    for (int o = 16; o; o >>= 1) v = fmaxf(v, __shfl_xor_sync(0xffffffffu, v, o));
    if ((t & 31) == 0) red[t >> 5] = v;
    __syncthreads();
    if (t < 32) {
        float s = (t < (int)(blockDim.x >> 5)) ? red[t] : -3.0e38f;
        #pragma unroll
        for (int o = 16; o; o >>= 1) s = fmaxf(s, __shfl_xor_sync(0xffffffffu, s, o));
        if (t == 0) red[0] = s;
    }
    __syncthreads();
    float r = red[0];
    __syncthreads();
    return r;
}

__global__ void seg_accum(const float* __restrict__ x, const int* __restrict__ labels){
    int i = blockIdx.x;
    int lab = labels[i];
    if (lab < 1) return;
    int c = lab - 1;
    int t = threadIdx.x;
    float4 v = ((const float4*)(x + (size_t)i * DD))[t];
    float* s = g_sums + (size_t)c * DD + 4 * t;
    asm volatile("red.global.add.v4.f32 [%0], {%1,%2,%3,%4};"
        :: "l"(s), "f"(v.x), "f"(v.y), "f"(v.z), "f"(v.w) : "memory");
    if (t == 0) atomicAdd(&g_cnts[c], 1.0f);
}

__global__ void compute_vt(const float* __restrict__ hist, const int* __restrict__ hcnt){
    int c = blockIdx.x;
    if (c == CC - 1) {
        for (int d = threadIdx.x; d < DD; d += blockDim.x)
            g_vth[(size_t)d * CC] = __float2half(0.f);
        return;
    }
    float cnt = g_cnts[c];
    bool has = cnt > 0.f;
    int nc = hcnt[c] + (has ? 1 : 0);
    if (nc < 1) nc = 1;
    float scale = (1.f - MUF) / (1.f - powf(MUF, (float)nc));
    float inv_cnt = has ? (1.f / cnt) : 0.f;
    for (int d = threadIdx.x; d < DD; d += blockDim.x) {
        float hv = hist[(size_t)c * DD + d];
        float nh = has ? (MUF * hv + g_sums[(size_t)c * DD + d] * inv_cnt) : hv;
        g_vth[(size_t)d * CC + (c + 1)] = __float2half(nh * scale);
    }
}

// fused per-row: CE(ctx) + masked MSE + softmax(w_logits in place) ; fp16 in/out
__global__ void loss_fuse(const half* __restrict__ CTXH, half* __restrict__ WLH,
                          const int* __restrict__ labels){
    __shared__ float red[32];
    int t = threadIdx.x, i = blockIdx.x;
    const half2* cr = (const half2*)(CTXH + (size_t)i * CC);
    half2* wr = (half2*)(WLH + (size_t)i * CC);
    int lab = labels[i];
    half2 c0 = cr[2*t], c1 = cr[2*t+1];
    half2 w0 = wr[2*t], w1 = wr[2*t+1];
    float vc[4] = {__half2float(c0.x), __half2float(c0.y), __half2float(c1.x), __half2float(c1.y)};
    float vb[4] = {__half2float(w0.x), __half2float(w0.y), __half2float(w1.x), __half2float(w1.y)};
    float mc = fmaxf(fmaxf(vc[0], vc[1]), fmaxf(vc[2], vc[3]));
    float mb = fmaxf(fmaxf(vb[0], vb[1]), fmaxf(vb[2], vb[3]));
    if (lab >= 0) {
        float ms = 0.f;
        #pragma unroll
        for (int j = 0; j < 4; j++) { float d = vc[j] - vb[j]; ms += d * d; }
        ms = block_sum(ms, red);
        if (t == 0) atomicAdd(&g_acc[2], ms);
    }
    mc = block_max(mc, red);
    float sc = 0.f;
    #pragma unroll
    for (int j = 0; j < 4; j++) sc += expf(vc[j] - mc);
    sc = block_sum(sc, red);
    if (t == 0 && lab >= 0) {
        atomicAdd(&g_acc[1], (logf(sc) + mc) - __half2float(CTXH[(size_t)i * CC + lab]));
        atomicAdd(&g_acc[3], 1.0f);
    }
    mb = block_max(mb, red);
    float sb = 0.f;
    #pragma unroll
    for (int j = 0; j < 4; j++) { vb[j] = expf(vb[j] - mb); sb += vb[j]; }
    sb = block_sum(sb, red);
    float inv = 1.0f / sb;
    wr[2*t]   = __floats2half2_rn(vb[0]*inv, vb[1]*inv);
    wr[2*t+1] = __floats2half2_rn(vb[2]*inv, vb[3]*inv);
}

// scalar loads: logits pointer may be only 4B-aligned
__global__ void ce_rows(const float* __restrict__ L, const int* __restrict__ labels){
    __shared__ float red[32];
    int t = threadIdx.x, i = blockIdx.x;
    const float* row = L + (size_t)i * CC;
    float v[4];
    v[0] = row[4*t]; v[1] = row[4*t+1]; v[2] = row[4*t+2]; v[3] = row[4*t+3];
    float mx = fmaxf(fmaxf(v[0], v[1]), fmaxf(v[2], v[3]));
    mx = block_max(mx, red);
    float s = 0.f;
    #pragma unroll
    for (int j = 0; j < 4; j++) s += expf(v[j] - mx);
    s = block_sum(s, red);
    if (t == 0) {
        int lab = labels[i];
        if (lab >= 0) atomicAdd(&g_acc[0], (logf(s) + mx) - row[lab]);
    }
}

__global__ void finalize(float* __restrict__ out_loss){
    float nv = fmaxf(g_acc[3], 1.0f);
    out_loss[0] = g_acc[0] / nv + g_acc[1] / nv + LAMF * g_acc[2] / (nv * (float)CC);
}

// ===================== HMMA fp16 GEMM (128x128 CTA, 64x32 warp, BK=64) ====
#define STAGE_B 32768
#define GSMEM (3 * STAGE_B)

__device__ __forceinline__ void issue_stage(
    uint32_t base, const half* __restrict__ A, const half* __restrict__ B,
    int K, int rowA0, int rowB0, int kt, int t)
{
    #pragma unroll
    for (int i = 0; i < 4; i++) {
        int idx = t + i * 256;
        int row = idx >> 3, ch = idx & 7;
        uint32_t off = (uint32_t)row * 128u + (uint32_t)((ch ^ (row & 7)) << 4);
        CPA16(base + off,           (const void*)(A + (size_t)(rowA0 + row) * K + kt + ch * 8));
        CPA16(base + 16384u + off,  (const void*)(B + (size_t)(rowB0 + row) * K + kt + ch * 8));
    }
    CPCOMMIT();
}

template <int EPI>
__global__ void __launch_bounds__(256, 2) gemm_hmma(
    const half* __restrict__ A, const half* __restrict__ B,
    const float* __restrict__ bias, float* __restrict__ Cout,
    half* __restrict__ Oh, const half* __restrict__ Xh,
    int M, int K)
{
    extern __shared__ char smem[];
    uint32_t sb = smem_u32(smem);
    const int t = threadIdx.x;
    const int wid = t >> 5, lane = t & 31;
    const int wm = (wid & 1) * 64;
    const int wn = (wid >> 1) * 32;
    const int grp = lane >> 3, lrow = lane & 7;
    const int rowA0 = blockIdx.y * 128, rowB0 = blockIdx.x * 128;
    const int S = K / 64;

    uint32_t aoff[4], boff[2];
    #pragma unroll
    for (int mf = 0; mf < 4; mf++) {
        int row = wm + mf * 16 + (grp & 1) * 8 + lrow;
        int cb  = grp >> 1;
        aoff[mf] = (uint32_t)row * 128u + (uint32_t)((cb ^ (row & 7)) << 4);
    }
    #pragma unroll
    for (int np = 0; np < 2; np++) {
        int row = wn + np * 16 + (grp >> 1) * 8 + lrow;
        int cb  = grp & 1;
        boff[np] = 16384u + (uint32_t)row * 128u + (uint32_t)((cb ^ (row & 7)) << 4);
    }

    float acc[4][4][4];
    #pragma unroll
    for (int i = 0; i < 4; i++)
        #pragma unroll
        for (int j = 0; j < 4; j++)
            #pragma unroll
            for (int q = 0; q < 4; q++) acc[i][j][q] = 0.f;

    issue_stage(sb,             A, B, K, rowA0, rowB0, 0,   t);
    issue_stage(sb + STAGE_B,   A, B, K, rowA0, rowB0, 64,  t);
    issue_stage(sb + 2*STAGE_B, A, B, K, rowA0, rowB0, 128, t);

    uint32_t stb  = sb;
    uint32_t rstb = sb + 2*STAGE_B;
    for (int s = 0; s < S; s++) {
        CPWAIT(1);
        __syncthreads();
        if (s >= 1) {
            if (s + 2 < S) issue_stage(rstb, A, B, K, rowA0, rowB0, (s + 2) * 64, t);
            else CPCOMMIT();
        }

        uint32_t bh[2][8];
        ldsm4(&bh[0][0], stb + boff[0]);
        ldsm4(&bh[0][4], stb + boff[1]);
        #pragma unroll
        for (int kh = 0; kh < 4; kh++) {
            uint32_t kx = (uint32_t)kh << 5;
            uint32_t ah[4][4];
            #pragma unroll
            for (int mf = 0; mf < 4; mf++) ldsm4(ah[mf], stb + (aoff[mf] ^ kx));
            if (kh < 3) {
                uint32_t kx2 = (uint32_t)(kh + 1) << 5;
                ldsm4(&bh[(kh+1)&1][0], stb + (boff[0] ^ kx2));
                ldsm4(&bh[(kh+1)&1][4], stb + (boff[1] ^ kx2));
            }
            const uint32_t* bc = bh[kh & 1];
            #pragma unroll
            for (int mf = 0; mf < 4; mf++)
                #pragma unroll
                for (int nf = 0; nf < 4; nf++)
                    mma_fp16(acc[mf][nf], ah[mf], bc[nf*2], bc[nf*2+1]);
        }
        rstb = stb;
        stb += STAGE_B;
        if (stb == sb + 3*STAGE_B) stb = sb;
    }

    const int r0 = rowA0 + wm + (lane >> 2);
    const int cbase = rowB0 + wn + (lane & 3) * 2;
    #pragma unroll
    for (int mf = 0; mf < 4; mf++) {
        #pragma unroll
        for (int nf = 0; nf < 4; nf++) {
            int col = cbase + nf * 8;
            float b0 = 0.f, b1 = 0.f;
            if (EPI == 2 || EPI == 5) { b0 = bias[col]; b1 = bias[col + 1]; }
            #pragma unroll
            for (int half_i = 0; half_i < 2; half_i++) {
                int row = r0 + mf * 16 + half_i * 8;
                float v0 = acc[mf][nf][half_i*2]   + b0;
                float v1 = acc[mf][nf][half_i*2+1] + b1;
                if (EPI == 2) {
                    v0 = 0.5f * v0 * (1.0f + erff(v0 * 0.70710678118654752f));
                    v1 = 0.5f * v1 * (1.0f + erff(v1 * 0.70710678118654752f));
                    *(half2*)(Oh + (size_t)row * M + col) = __floats2half2_rn(v0, v1);
                } else if (EPI == 5) {
                    *(half2*)(Oh + (size_t)row * M + col) = __floats2half2_rn(v0, v1);
                } else if (EPI == 4) {
                    float g = bias[row];
                    size_t o = (size_t)row * M + col;
                    half2 xv = *(const half2*)(Xh + o);
                    float u0 = g * __half2float(xv.x) + (1.f - g) * v0;
                    float u1 = g * __half2float(xv.y) + (1.f - g) * v1;
                    *(half2*)(Oh + o) = __floats2half2_rn(u0, u1);
                } else if (EPI == 3) {
                    Cout[(size_t)row * M + col]     = v0;
                    Cout[(size_t)row * M + col + 1] = v1;
                } else {
                    *(float2*)(Cout + (size_t)row * M + col) = make_float2(v0, v1);
                }
            }
        }
    }
}

// ===================== launch =====================
#define SYM(p, s) cudaGetSymbolAddress((void**)&p, s)

extern "C" void kernel_launch(void* const* d_in, const int* in_sizes, int n_in,
                              void* d_out, int out_size) {
    const float* x          = (const float*)d_in[0];
    const float* x_ctx      = (const float*)d_in[1];
    const int*   labels     = (const int*)d_in[2];
    const float* classifier = (const float*)d_in[3];
    const float* W_ctx      = (const float*)d_in[4];
    const float* b_ctx      = (const float*)d_in[5];
    const float* W_g        = (const float*)d_in[6];
    const float* b_g        = (const float*)d_in[7];
    const float* W1         = (const float*)d_in[8];
    const float* b1         = (const float*)d_in[9];
    const float* W2         = (const float*)d_in[10];
    const float* b2         = (const float*)d_in[11];
    const float* hist       = (const float*)d_in[12];
    const int*   hcnt       = (const int*)d_in[13];

    cudaFuncSetAttribute(gemm_hmma<0>, cudaFuncAttributeMaxDynamicSharedMemorySize, GSMEM);
    cudaFuncSetAttribute(gemm_hmma<2>, cudaFuncAttributeMaxDynamicSharedMemorySize, GSMEM);
    cudaFuncSetAttribute(gemm_hmma<3>, cudaFuncAttributeMaxDynamicSharedMemorySize, GSMEM);
    cudaFuncSetAttribute(gemm_hmma<4>, cudaFuncAttributeMaxDynamicSharedMemorySize, GSMEM);
    cudaFuncSetAttribute(gemm_hmma<5>, cudaFuncAttributeMaxDynamicSharedMemorySize, GSMEM);

    float *p_red, *p_buf, *p_gate;
    half *p_xh,*p_cxh,*p_hh,*p_uh,*p_ctxh,*p_wlh,*p_vth,*p_Wch,*p_W1h,*p_W2h,*p_Kh;
    SYM(p_red,g_red);   SYM(p_buf,g_buf);   SYM(p_gate,g_gate);
    SYM(p_xh,g_xh);     SYM(p_cxh,g_cxh);   SYM(p_hh,g_hh);  SYM(p_uh,g_uh);
    SYM(p_ctxh,g_ctxh); SYM(p_wlh,g_wlh);   SYM(p_vth,g_vth);
    SYM(p_Wch,g_Wch);   SYM(p_W1h,g_W1h);   SYM(p_W2h,g_W2h); SYM(p_Kh,g_Kh);

    const bool fork = g_ss.ok;
    cudaStream_t sB = fork ? g_ss.s : (cudaStream_t)0;

    cudaMemsetAsync(p_red, 0, sizeof(float) * ((size_t)(CC-1)*DD + (CC-1) + 8));
    if (fork) {
        cudaEventRecord(g_ss.fork, 0);
        cudaStreamWaitEvent(sB, g_ss.fork, 0);
    }

    // side chain B: history + converts + gate (fp16 x, after cvt_rest)
    seg_accum<<<NN, 192, 0, sB>>>(x, labels);
    compute_vt<<<CC, 256, 0, sB>>>(hist, hcnt);
    {
        size_t n8 = (size_t)NN*DD/8 + (size_t)DD*DD/8 + 2*(size_t)CC*DD/8;
        cvt_rest<<<(unsigned)((n8 + 255)/256), 256, 0, sB>>>(x, W1, W2, classifier);
    }
    gate_gemv<<<NN/8, 256, 0, sB>>>(W_g, b_g);
    if (fork) cudaEventRecord(g_ss.join, sB);

    // main chain: ctx converts then ctx GEMM
    {
        size_t n8 = (size_t)NN*DD/8 + (size_t)CC*DD/8;
        cvt_ctx<<<(unsigned)((n8 + 255)/256), 256>>>(x_ctx, W_ctx);
    }

    dim3 gNC(CC / 128, NN / 128);
    dim3 gND(DD / 128, NN / 128);

    gemm_hmma<5><<<gNC, 256, GSMEM>>>(p_cxh, p_Wch, b_ctx, 0, p_ctxh, 0, CC, DD);

    if (fork) cudaStreamWaitEvent(0, g_ss.join, 0);

    gemm_hmma<2><<<gND, 256, GSMEM>>>(p_xh, p_W1h, b1, 0, p_hh, 0, DD, DD);
    gemm_hmma<5><<<gNC, 256, GSMEM>>>(p_hh, p_W2h, b2, 0, p_wlh, 0, CC, DD);
    loss_fuse<<<NN, 256>>>(p_ctxh, p_wlh, labels);

    gemm_hmma<4><<<gND, 256, GSMEM>>>(p_wlh, p_vth, p_gate, 0, p_uh, p_xh, DD, CC);

    float* outF = (float*)d_out;
    size_t NCt = (size_t)NN * CC;
    if ((size_t)out_size >= NCt + 1) {
        float* logits = outF + ((size_t)out_size - NCt);
        if ((((uintptr_t)logits) & 7) == 0)
            gemm_hmma<0><<<gNC, 256, GSMEM>>>(p_uh, p_Kh, 0, logits, 0, 0, CC, DD);
        else
            gemm_hmma<3><<<gNC, 256, GSMEM>>>(p_uh, p_Kh, 0, logits, 0, 0, CC, DD);
        ce_rows<<<NN, 256>>>(logits, labels);
        finalize<<<1, 1>>>(outF);
    } else if ((size_t)out_size == NCt) {
        gemm_hmma<0><<<gNC, 256, GSMEM>>>(p_uh, p_Kh, 0, outF, 0, 0, CC, DD);
        ce_rows<<<NN, 256>>>(outF, labels);
    } else {
        gemm_hmma<0><<<gNC, 256, GSMEM>>>(p_uh, p_Kh, 0, p_buf, 0, 0, CC, DD);
        ce_rows<<<NN, 256>>>(p_buf, labels);
        finalize<<<1, 1>>>(outF);
    }
}